// round 3
// baseline (speedup 1.0000x reference)
#include <cuda_runtime.h>
#include <math.h>

#define NEG_INF (__int_as_float(0xff800000))

// Problem constants
#define BB 4
#define SS 2048
#define EE 1024
#define AA 64

// Scratch: K = emb @ Wk^T  [B, S, A] fp32 = 2 MB
__device__ float g_K[BB * SS * AA];

// ---------------------------------------------------------------------------
// Kernel 1: K projection.  C[r][a] = sum_e emb[r][e] * Wk[a][e]
// NT GEMM: both operands row-major with contiguous reduction dim.
// grid = 128 (64 rows each), block = 256 (16x16), 4x4 strided fragments.
// ---------------------------------------------------------------------------
__global__ __launch_bounds__(256, 1) void k_proj_kernel(
    const float* __restrict__ emb, const float* __restrict__ Wk)
{
    __shared__ float Es[64][68];
    __shared__ float Ws[64][68];

    const int t  = threadIdx.x;
    const int ty = t >> 4;
    const int tx = t & 15;
    const int rowbase = blockIdx.x * 64;

    float acc[4][4];
#pragma unroll
    for (int i = 0; i < 4; i++)
#pragma unroll
        for (int j = 0; j < 4; j++) acc[i][j] = 0.f;

    for (int et = 0; et < EE; et += 64) {
        __syncthreads();
#pragma unroll
        for (int g = 0; g < 4; g++) {
            int idx = t + g * 256;          // 1024 float4 slots = 64x64 floats
            int r  = idx >> 4;
            int c4 = idx & 15;
            *(float4*)&Es[r][c4 * 4] =
                *(const float4*)&emb[(rowbase + r) * EE + et + c4 * 4];
            *(float4*)&Ws[r][c4 * 4] =
                *(const float4*)&Wk[r * EE + et + c4 * 4];
        }
        __syncthreads();

#pragma unroll
        for (int e4 = 0; e4 < 16; e4++) {
            float4 a0 = *(const float4*)&Es[ty      ][e4 * 4];
            float4 a1 = *(const float4*)&Es[ty + 16][e4 * 4];
            float4 a2 = *(const float4*)&Es[ty + 32][e4 * 4];
            float4 a3 = *(const float4*)&Es[ty + 48][e4 * 4];
#pragma unroll
            for (int j = 0; j < 4; j++) {
                float4 b = *(const float4*)&Ws[tx + 16 * j][e4 * 4];
                acc[0][j] += a0.x*b.x + a0.y*b.y + a0.z*b.z + a0.w*b.w;
                acc[1][j] += a1.x*b.x + a1.y*b.y + a1.z*b.z + a1.w*b.w;
                acc[2][j] += a2.x*b.x + a2.y*b.y + a2.z*b.z + a2.w*b.w;
                acc[3][j] += a3.x*b.x + a3.y*b.y + a3.z*b.z + a3.w*b.w;
            }
        }
    }

#pragma unroll
    for (int i = 0; i < 4; i++) {
        int row = rowbase + ty + 16 * i;
#pragma unroll
        for (int j = 0; j < 4; j++)
            g_K[row * AA + tx + 16 * j] = acc[i][j];
    }
}

// ---------------------------------------------------------------------------
// Kernel 2: causal flash attention with q = k = v = g_K.
// grid = (32 pairs, 4 batches), block = 256 (16x16).
// Each block processes query tiles {p, 63-p} (BQ=32 rows each) so every
// block performs an equal number (~33) of BK=64 key-tile iterations.
// Score fragment: rows ty+16*rr (rr<2), keys tx+16*cc (cc<4).
// Output fragment: rows ty+16*rr, dims tx*4+j (float4).
// ---------------------------------------------------------------------------
__global__ __launch_bounds__(256, 1) void attn_kernel(float* __restrict__ out)
{
    __shared__ float Qs[32][68];
    __shared__ float Ks[64][68];   // serves as both K and V tile (v == k)
    __shared__ float Ps[32][68];

    const int t  = threadIdx.x;
    const int ty = t >> 4;
    const int tx = t & 15;
    const int b  = blockIdx.y;
    const float* __restrict__ Kb = g_K + b * SS * AA;

    for (int half = 0; half < 2; half++) {
        const int qt = half ? (63 - (int)blockIdx.x) : (int)blockIdx.x;

        __syncthreads();   // protect smem reuse from previous half
#pragma unroll
        for (int g = 0; g < 2; g++) {
            int idx = t + g * 256;          // 512 float4 = 32x64 floats
            int r  = idx >> 4;
            int c4 = idx & 15;
            *(float4*)&Qs[r][c4 * 4] =
                *(const float4*)&Kb[(qt * 32 + r) * 64 + c4 * 4];
        }

        float4 o0 = make_float4(0.f, 0.f, 0.f, 0.f);
        float4 o1 = make_float4(0.f, 0.f, 0.f, 0.f);
        float m0 = NEG_INF, m1 = NEG_INF;
        float l0 = 0.f, l1 = 0.f;
        const int grow0 = qt * 32 + ty;
        const int grow1 = grow0 + 16;
        const int ktmax = (qt * 32 + 31) >> 6;   // inclusive

        for (int kt = 0; kt <= ktmax; kt++) {
            __syncthreads();    // previous iter's PV done reading Ks/Ps
#pragma unroll
            for (int g = 0; g < 4; g++) {
                int idx = t + g * 256;      // 1024 float4 = 64x64 floats
                int r  = idx >> 4;
                int c4 = idx & 15;
                *(float4*)&Ks[r][c4 * 4] =
                    *(const float4*)&Kb[(kt * 64 + r) * 64 + c4 * 4];
            }
            __syncthreads();

            // ---- scores S = Q . K^T ----
            float s0[4] = {0.f, 0.f, 0.f, 0.f};
            float s1[4] = {0.f, 0.f, 0.f, 0.f};
#pragma unroll
            for (int d4 = 0; d4 < 16; d4++) {
                float4 q0 = *(const float4*)&Qs[ty     ][d4 * 4];
                float4 q1 = *(const float4*)&Qs[ty + 16][d4 * 4];
#pragma unroll
                for (int cc = 0; cc < 4; cc++) {
                    float4 k = *(const float4*)&Ks[tx + 16 * cc][d4 * 4];
                    s0[cc] += q0.x*k.x + q0.y*k.y + q0.z*k.z + q0.w*k.w;
                    s1[cc] += q1.x*k.x + q1.y*k.y + q1.z*k.z + q1.w*k.w;
                }
            }

            // ---- scale + faithful mask: (col > row) OR (value == 0) ----
#pragma unroll
            for (int cc = 0; cc < 4; cc++) {
                int gc = kt * 64 + tx + 16 * cc;
                float v0 = s0[cc] * 0.125f;
                float v1 = s1[cc] * 0.125f;
                s0[cc] = (gc > grow0 || v0 == 0.f) ? NEG_INF : v0;
                s1[cc] = (gc > grow1 || v1 == 0.f) ? NEG_INF : v1;
            }

            // ---- online softmax, row group 0 ----
            {
                float tm = fmaxf(fmaxf(s0[0], s0[1]), fmaxf(s0[2], s0[3]));
                tm = fmaxf(tm, __shfl_xor_sync(0xffffffffu, tm, 8));
                tm = fmaxf(tm, __shfl_xor_sync(0xffffffffu, tm, 4));
                tm = fmaxf(tm, __shfl_xor_sync(0xffffffffu, tm, 2));
                tm = fmaxf(tm, __shfl_xor_sync(0xffffffffu, tm, 1));
                float mn   = fmaxf(m0, tm);
                float corr = (m0 == mn) ? 1.f : __expf(m0 - mn);
                bool  dead = (mn == NEG_INF);
                float rs = 0.f;
#pragma unroll
                for (int cc = 0; cc < 4; cc++) {
                    float p = dead ? 0.f : __expf(s0[cc] - mn);
                    s0[cc] = p;
                    rs += p;
                }
                rs += __shfl_xor_sync(0xffffffffu, rs, 8);
                rs += __shfl_xor_sync(0xffffffffu, rs, 4);
                rs += __shfl_xor_sync(0xffffffffu, rs, 2);
                rs += __shfl_xor_sync(0xffffffffu, rs, 1);
                l0 = l0 * corr + rs;
                m0 = mn;
                o0.x *= corr; o0.y *= corr; o0.z *= corr; o0.w *= corr;
            }
            // ---- online softmax, row group 1 ----
            {
                float tm = fmaxf(fmaxf(s1[0], s1[1]), fmaxf(s1[2], s1[3]));
                tm = fmaxf(tm, __shfl_xor_sync(0xffffffffu, tm, 8));
                tm = fmaxf(tm, __shfl_xor_sync(0xffffffffu, tm, 4));
                tm = fmaxf(tm, __shfl_xor_sync(0xffffffffu, tm, 2));
                tm = fmaxf(tm, __shfl_xor_sync(0xffffffffu, tm, 1));
                float mn   = fmaxf(m1, tm);
                float corr = (m1 == mn) ? 1.f : __expf(m1 - mn);
                bool  dead = (mn == NEG_INF);
                float rs = 0.f;
#pragma unroll
                for (int cc = 0; cc < 4; cc++) {
                    float p = dead ? 0.f : __expf(s1[cc] - mn);
                    s1[cc] = p;
                    rs += p;
                }
                rs += __shfl_xor_sync(0xffffffffu, rs, 8);
                rs += __shfl_xor_sync(0xffffffffu, rs, 4);
                rs += __shfl_xor_sync(0xffffffffu, rs, 2);
                rs += __shfl_xor_sync(0xffffffffu, rs, 1);
                l1 = l1 * corr + rs;
                m1 = mn;
                o1.x *= corr; o1.y *= corr; o1.z *= corr; o1.w *= corr;
            }

            // ---- stage P in smem ----
#pragma unroll
            for (int cc = 0; cc < 4; cc++) {
                Ps[ty     ][tx + 16 * cc] = s0[cc];
                Ps[ty + 16][tx + 16 * cc] = s1[cc];
            }
            __syncthreads();

            // ---- O += P . V  (V tile == Ks) ----
#pragma unroll
            for (int k4 = 0; k4 < 16; k4++) {
                float4 p0 = *(const float4*)&Ps[ty     ][k4 * 4];
                float4 p1 = *(const float4*)&Ps[ty + 16][k4 * 4];
                const float* pp0 = (const float*)&p0;
                const float* pp1 = (const float*)&p1;
#pragma unroll
                for (int j = 0; j < 4; j++) {
                    float4 v = *(const float4*)&Ks[k4 * 4 + j][tx * 4];
                    float a0 = pp0[j], a1 = pp1[j];
                    o0.x += a0 * v.x; o0.y += a0 * v.y;
                    o0.z += a0 * v.z; o0.w += a0 * v.w;
                    o1.x += a1 * v.x; o1.y += a1 * v.y;
                    o1.z += a1 * v.z; o1.w += a1 * v.w;
                }
            }
        }

        // ---- epilogue: normalize + store ----
        float inv0 = 1.f / l0;
        float inv1 = 1.f / l1;
        o0.x *= inv0; o0.y *= inv0; o0.z *= inv0; o0.w *= inv0;
        o1.x *= inv1; o1.y *= inv1; o1.z *= inv1; o1.w *= inv1;

        int row0 = b * SS + qt * 32 + ty;
        *(float4*)&out[(row0     ) * 64 + tx * 4] = o0;
        *(float4*)&out[(row0 + 16) * 64 + tx * 4] = o1;
    }
}

// ---------------------------------------------------------------------------
extern "C" void kernel_launch(void* const* d_in, const int* in_sizes, int n_in,
                              void* d_out, int out_size)
{
    const float* emb = (const float*)d_in[0];   // [4, 2048, 1024]
    const float* Wk  = (const float*)d_in[1];   // [64, 1024]
    float* out = (float*)d_out;                 // [4, 2048, 64]
    (void)in_sizes; (void)n_in; (void)out_size;

    k_proj_kernel<<<128, 256>>>(emb, Wk);
    attn_kernel<<<dim3(32, 4), 256>>>(out);
}